// round 10
// baseline (speedup 1.0000x reference)
#include <cuda_runtime.h>
#include <cstdint>

#define B 8
#define O 2048
#define Q 2048
#define D 128
#define KT 10      // expansion terms k = 0..9 (remainder <= 7.5e-7 rel at x<=1)
#define GS 12      // g_s row stride (floats), 16B-aligned
#define NCH 64     // obs chunks per batch
#define CH 32      // obs rows per chunk

// Scratch (allocation-free rule: device globals; zero-initialized at load).
// g_M / g_msum_in are atomic accumulators; kernel B consumes AND re-zeros
// them each call, so every kernel_launch invocation starts from zeros.
__device__ float g_M[B * KT * D];        // accumulated moments
__device__ float g_msum_in[B * KT];      // accumulated weight sums
__device__ __align__(16) float g_Mp[B * KT * D];   // projected moments
__device__ __align__(16) float g_msum[B * KT];     // weight-sum moments (for C)

__constant__ float c_invk[KT] = {0.f, 1.f, 1.f/2, 1.f/3, 1.f/4, 1.f/5, 1.f/6,
                                 1.f/7, 1.f/8, 1.f/9};

// ---------------------------------------------------------------------------
// Kernel A: per (batch, 32-obs chunk) moments, reduced across CTAs via RED.
//   g_k(o) = mask_o * exp(-0.5*c2*t_o^2) * (c2*t_o)^k / k!
//   g_M[b][k][e] += sum_o g_k(o)*emb[o][e] ;  g_msum_in[b][k] += sum_o g_k(o)
// 512 CTAs x 512 threads. Thread: e = tid&127, quarter = tid>>7 owns 8 rows.
// ---------------------------------------------------------------------------
__global__ __launch_bounds__(512) void k_moments(
    const float* __restrict__ obs_emb,
    const float* __restrict__ obs_times,
    const float* __restrict__ obs_mask,
    const float* __restrict__ log_sigma)
{
    __shared__ __align__(16) float g_s[CH * GS];        // 10 used, pad to 12
    __shared__ __align__(16) float red[3 * KT * D];     // quarters 1..3 (15KB)

    const int tid = threadIdx.x;
    const int c   = blockIdx.x;
    const int b   = blockIdx.y;
    const int o0  = c * CH;

    const int e  = tid & 127;
    const int qa = tid >> 7;            // 0..3, 8 rows each

    // ---- front-batched emb loads (independent of g_s) ----
    const float* ebase = obs_emb + ((size_t)(b * O) + o0 + qa * 8) * D + e;
    float x[8];
#pragma unroll
    for (int oo = 0; oo < 8; ++oo) x[oo] = __ldg(ebase + (size_t)oo * D);

    const float c2 = __expf(-2.0f * log_sigma[0]);   // 1/sigma^2

    // Phase 1: 32 threads compute g_k rows (overlaps with loads above)
    if (tid < CH) {
        const int o = o0 + tid;
        const float t  = obs_times[b * O + o];
        const float mk = obs_mask[b * O + o];
        const float xx = c2 * t;
        float g = mk * __expf(-0.5f * c2 * t * t);
        g_s[tid * GS + 0] = g;
#pragma unroll
        for (int k = 1; k < KT; ++k) {
            g *= xx * c_invk[k];
            g_s[tid * GS + k] = g;
        }
    }
    __syncthreads();

    // ms partials -> atomic accumulate
    if (tid < KT) {
        float s = 0.0f;
#pragma unroll
        for (int o = 0; o < CH; ++o) s += g_s[o * GS + tid];
        atomicAdd(&g_msum_in[b * KT + tid], s);
    }

    // Phase 2: accumulate moments over 8 rows per thread.
    float acc[KT];
#pragma unroll
    for (int k = 0; k < KT; ++k) acc[k] = 0.0f;

    const float* gbase = g_s + qa * 8 * GS;
#pragma unroll
    for (int oo = 0; oo < 8; ++oo) {
        const float xv = x[oo];
        const float4 ga = *(const float4*)(gbase + oo * GS + 0);
        const float4 gb = *(const float4*)(gbase + oo * GS + 4);
        const float2 gc = *(const float2*)(gbase + oo * GS + 8);
        acc[0] = fmaf(ga.x, xv, acc[0]);   acc[1] = fmaf(ga.y, xv, acc[1]);
        acc[2] = fmaf(ga.z, xv, acc[2]);   acc[3] = fmaf(ga.w, xv, acc[3]);
        acc[4] = fmaf(gb.x, xv, acc[4]);   acc[5] = fmaf(gb.y, xv, acc[5]);
        acc[6] = fmaf(gb.z, xv, acc[6]);   acc[7] = fmaf(gb.w, xv, acc[7]);
        acc[8] = fmaf(gc.x, xv, acc[8]);   acc[9] = fmaf(gc.y, xv, acc[9]);
    }

    // combine the four quarters via SMEM (quarters 1..3 store, quarter 0 REDs)
    if (qa > 0) {
        float* dst = red + (qa - 1) * KT * D + e;
#pragma unroll
        for (int k = 0; k < KT; ++k) dst[k * D] = acc[k];
    }
    __syncthreads();
    if (qa == 0) {
        float* dst = g_M + (size_t)(b * KT) * D + e;
        const float* r0 = red + e;
#pragma unroll
        for (int k = 0; k < KT; ++k) {
            const float v = acc[k] + r0[k * D] + r0[KT * D + k * D]
                          + r0[2 * KT * D + k * D];
            atomicAdd(dst + k * D, v);      // RED.ADD, coalesced across e
        }
    }
}

// ---------------------------------------------------------------------------
// Kernel B: project accumulated moments through W; consume-and-rezero the
// atomic buffers so the next kernel_launch call starts from zeros.
//   Mp[b][k][e'] = sum_e W[e'][e] * g_M[b][k][e]
// One CTA per (b, k), 128 threads.
// ---------------------------------------------------------------------------
__global__ __launch_bounds__(128) void k_project(
    const float* __restrict__ W_proj)
{
    __shared__ __align__(16) float m_s[D];
    const int e = threadIdx.x;
    const int k = blockIdx.x % KT;
    const int b = blockIdx.x / KT;

    float* mcell = g_M + (size_t)(b * KT + k) * D + e;
    m_s[e] = *mcell;
    *mcell = 0.0f;                       // restore zero state
    if (e == 0) {
        g_msum[b * KT + k] = g_msum_in[b * KT + k];
        g_msum_in[b * KT + k] = 0.0f;    // restore zero state
    }
    __syncthreads();

    // thread e = output dim: dot(W[e][:], m)
    const float4* wrow = (const float4*)(W_proj + (size_t)e * D);
    float dot = 0.0f;
#pragma unroll
    for (int i = 0; i < D / 4; ++i) {
        float4 w4 = wrow[i];
        const float4 m4 = *(const float4*)&m_s[i * 4];
        dot += w4.x * m4.x + w4.y * m4.y + w4.z * m4.z + w4.w * m4.w;
    }
    g_Mp[(size_t)(b * KT + k) * D + e] = dot;
}

// ---------------------------------------------------------------------------
// Kernel C: combine. out[q][e'] = (sum_k f_k(q) Mp[k][e']) / (sum_k f_k msum[k]) + b[e']
// Thread owns 4 e-cols; handles 2 q's with INTERLEAVED f-chains (2x ILP on the
// serial f*=qt dependency). Mp/msum in registers. 1024 CTAs, 256 threads.
// ---------------------------------------------------------------------------
__global__ __launch_bounds__(256) void k_combine(
    const float* __restrict__ query_times,
    const float* __restrict__ log_sigma,
    const float* __restrict__ b_proj,
    float* __restrict__ out)
{
    const int tid = threadIdx.x;
    const int b   = blockIdx.y;
    const int q0  = blockIdx.x * 16;
    const int e   = (tid & 31) * 4;
    const int qh  = tid >> 5;          // 0..7, 2 q's each

    const float* qtp = query_times + b * Q + q0 + qh * 2;
    const float qt0 = qtp[0];
    const float qt1 = qtp[1];

    float4 mp[KT];
    float  ms[KT];
    const float* mpb = g_Mp + (size_t)b * KT * D + e;
    const float* msb = g_msum + b * KT;
#pragma unroll
    for (int k = 0; k < KT; ++k) {
        mp[k] = *(const float4*)(mpb + k * D);
        ms[k] = msb[k];
    }

    const float c2 = __expf(-2.0f * log_sigma[0]);
    const float4 bp = *(const float4*)&b_proj[e];
    float* ob = out + ((size_t)(b * Q) + q0 + qh * 2) * D + e;

    float f0 = __expf(-0.5f * c2 * qt0 * qt0);
    float f1 = __expf(-0.5f * c2 * qt1 * qt1);
    float4 n0, n1;
    n0.x = f0 * mp[0].x; n0.y = f0 * mp[0].y; n0.z = f0 * mp[0].z; n0.w = f0 * mp[0].w;
    n1.x = f1 * mp[0].x; n1.y = f1 * mp[0].y; n1.z = f1 * mp[0].z; n1.w = f1 * mp[0].w;
    float d0 = f0 * ms[0];
    float d1 = f1 * ms[0];
#pragma unroll
    for (int k = 1; k < KT; ++k) {
        f0 *= qt0;
        f1 *= qt1;
        n0.x = fmaf(f0, mp[k].x, n0.x); n0.y = fmaf(f0, mp[k].y, n0.y);
        n0.z = fmaf(f0, mp[k].z, n0.z); n0.w = fmaf(f0, mp[k].w, n0.w);
        n1.x = fmaf(f1, mp[k].x, n1.x); n1.y = fmaf(f1, mp[k].y, n1.y);
        n1.z = fmaf(f1, mp[k].z, n1.z); n1.w = fmaf(f1, mp[k].w, n1.w);
        d0 = fmaf(f0, ms[k], d0);
        d1 = fmaf(f1, ms[k], d1);
    }
    const float i0 = __fdividef(1.0f, fmaxf(d0, 1e-8f));
    const float i1 = __fdividef(1.0f, fmaxf(d1, 1e-8f));
    float4 v0, v1;
    v0.x = fmaf(n0.x, i0, bp.x); v0.y = fmaf(n0.y, i0, bp.y);
    v0.z = fmaf(n0.z, i0, bp.z); v0.w = fmaf(n0.w, i0, bp.w);
    v1.x = fmaf(n1.x, i1, bp.x); v1.y = fmaf(n1.y, i1, bp.y);
    v1.z = fmaf(n1.z, i1, bp.z); v1.w = fmaf(n1.w, i1, bp.w);
    *(float4*)(ob)     = v0;
    *(float4*)(ob + D) = v1;
}

// ---------------------------------------------------------------------------
extern "C" void kernel_launch(void* const* d_in, const int* in_sizes, int n_in,
                              void* d_out, int out_size) {
    const float* obs_emb     = (const float*)d_in[0];
    const float* obs_times   = (const float*)d_in[1];
    const float* query_times = (const float*)d_in[2];
    const float* obs_mask    = (const float*)d_in[3];
    const float* log_sigma   = (const float*)d_in[4];
    const float* W_proj      = (const float*)d_in[5];
    const float* b_proj      = (const float*)d_in[6];
    float* out = (float*)d_out;

    dim3 gA(NCH, B);
    k_moments<<<gA, 512>>>(obs_emb, obs_times, obs_mask, log_sigma);
    k_project<<<B * KT, 128>>>(W_proj);
    dim3 gC(Q / 16, B);
    k_combine<<<gC, 256>>>(query_times, log_sigma, b_proj, out);
}

// round 11
// speedup vs baseline: 1.1326x; 1.1326x over previous
#include <cuda_runtime.h>
#include <cstdint>

#define B 8
#define O 2048
#define Q 2048
#define D 128
#define KT 10      // expansion terms k = 0..9 (remainder <= 7.5e-7 rel at x<=1)
#define GS 12      // g_s row stride (floats), 16B-aligned
#define NCH 64     // obs chunks per batch
#define CH 32      // obs rows per chunk

// Scratch (allocation-free rule: device globals; zero-initialized at load).
// g_M / g_msum_in are atomic accumulators; kernel B consumes AND re-zeros
// them each call, so every kernel_launch invocation starts from zeros.
__device__ float g_M[B * KT * D];        // accumulated moments
__device__ float g_msum_in[B * KT];      // accumulated weight sums
__device__ __align__(16) float g_Mp[B * KT * D];   // projected moments
__device__ __align__(16) float g_msum[B * KT];     // weight-sum moments (for C)

__constant__ float c_invk[KT] = {0.f, 1.f, 1.f/2, 1.f/3, 1.f/4, 1.f/5, 1.f/6,
                                 1.f/7, 1.f/8, 1.f/9};

// PDL: wait for the upstream grid's memory to be visible (sm_90+ PTX).
__device__ __forceinline__ void grid_dep_wait() {
    asm volatile("griddepcontrol.wait;" ::: "memory");
}

// ---------------------------------------------------------------------------
// Kernel A: per (batch, 32-obs chunk) moments, reduced across CTAs via RED.
//   g_k(o) = mask_o * exp(-0.5*c2*t_o^2) * (c2*t_o)^k / k!
//   g_M[b][k][e] += sum_o g_k(o)*emb[o][e] ;  g_msum_in[b][k] += sum_o g_k(o)
// R5 shape: 512 CTAs x 256 threads, e = tid&127, half = tid>>7 owns 16 rows,
// x loads in-loop (ptxas software-pipelines them).
// ---------------------------------------------------------------------------
__global__ __launch_bounds__(256) void k_moments(
    const float* __restrict__ obs_emb,
    const float* __restrict__ obs_times,
    const float* __restrict__ obs_mask,
    const float* __restrict__ log_sigma)
{
    __shared__ __align__(16) float g_s[CH * GS];   // 10 used, pad to 12
    __shared__ __align__(16) float red[KT * D];

    const int tid = threadIdx.x;
    const int c   = blockIdx.x;
    const int b   = blockIdx.y;
    const int o0  = c * CH;
    const float c2 = __expf(-2.0f * log_sigma[0]);   // 1/sigma^2

    // Phase 1: 32 threads compute g_k rows
    if (tid < CH) {
        const int o = o0 + tid;
        const float t  = obs_times[b * O + o];
        const float mk = obs_mask[b * O + o];
        const float xx = c2 * t;
        float g = mk * __expf(-0.5f * c2 * t * t);
        g_s[tid * GS + 0] = g;
#pragma unroll
        for (int k = 1; k < KT; ++k) {
            g *= xx * c_invk[k];
            g_s[tid * GS + k] = g;
        }
    }
    __syncthreads();

    // ms partials -> atomic accumulate
    if (tid < KT) {
        float s = 0.0f;
#pragma unroll
        for (int o = 0; o < CH; ++o) s += g_s[o * GS + tid];
        atomicAdd(&g_msum_in[b * KT + tid], s);
    }

    // Phase 2: accumulate moments over 16 rows per thread, loads in-loop.
    const int e    = tid & 127;
    const int half = tid >> 7;
    float acc[KT];
#pragma unroll
    for (int k = 0; k < KT; ++k) acc[k] = 0.0f;

    const float* ebase = obs_emb + ((size_t)(b * O) + o0 + half * 16) * D + e;
    const float* gbase = g_s + half * 16 * GS;
#pragma unroll
    for (int oo = 0; oo < 16; ++oo) {
        const float xv = ebase[(size_t)oo * D];
        const float4 ga = *(const float4*)(gbase + oo * GS + 0);
        const float4 gb = *(const float4*)(gbase + oo * GS + 4);
        const float2 gc = *(const float2*)(gbase + oo * GS + 8);
        acc[0] = fmaf(ga.x, xv, acc[0]);   acc[1] = fmaf(ga.y, xv, acc[1]);
        acc[2] = fmaf(ga.z, xv, acc[2]);   acc[3] = fmaf(ga.w, xv, acc[3]);
        acc[4] = fmaf(gb.x, xv, acc[4]);   acc[5] = fmaf(gb.y, xv, acc[5]);
        acc[6] = fmaf(gb.z, xv, acc[6]);   acc[7] = fmaf(gb.w, xv, acc[7]);
        acc[8] = fmaf(gc.x, xv, acc[8]);   acc[9] = fmaf(gc.y, xv, acc[9]);
    }

    // combine the two halves via SMEM, then RED.ADD into g_M
    if (half == 1) {
#pragma unroll
        for (int k = 0; k < KT; ++k) red[k * D + e] = acc[k];
    }
    __syncthreads();
    if (half == 0) {
        float* dst = g_M + (size_t)(b * KT) * D + e;
        const float* r0 = red + e;
#pragma unroll
        for (int k = 0; k < KT; ++k)
            atomicAdd(dst + k * D, acc[k] + r0[k * D]);
    }
}

// ---------------------------------------------------------------------------
// Kernel B: project accumulated moments through W; consume-and-rezero the
// atomic buffers so the next kernel_launch call starts from zeros.
//   Mp[b][k][e'] = sum_e W[e'][e] * g_M[b][k][e]
// One CTA per (b, k), 128 threads. PDL: waits on A's completion.
// ---------------------------------------------------------------------------
__global__ __launch_bounds__(128) void k_project(
    const float* __restrict__ W_proj)
{
    __shared__ __align__(16) float m_s[D];
    const int e = threadIdx.x;
    const int k = blockIdx.x % KT;
    const int b = blockIdx.x / KT;

    grid_dep_wait();   // A's g_M / g_msum_in now visible

    float* mcell = g_M + (size_t)(b * KT + k) * D + e;
    m_s[e] = *mcell;
    *mcell = 0.0f;                       // restore zero state
    if (e == 0) {
        g_msum[b * KT + k] = g_msum_in[b * KT + k];
        g_msum_in[b * KT + k] = 0.0f;    // restore zero state
    }
    __syncthreads();

    // thread e = output dim: dot(W[e][:], m)
    const float4* wrow = (const float4*)(W_proj + (size_t)e * D);
    float dot = 0.0f;
#pragma unroll
    for (int i = 0; i < D / 4; ++i) {
        float4 w4 = wrow[i];
        const float4 m4 = *(const float4*)&m_s[i * 4];
        dot += w4.x * m4.x + w4.y * m4.y + w4.z * m4.z + w4.w * m4.w;
    }
    g_Mp[(size_t)(b * KT + k) * D + e] = dot;
}

// ---------------------------------------------------------------------------
// Kernel C: combine. out[q][e'] = (sum_k f_k(q) Mp[k][e']) / (sum_k f_k msum[k]) + b[e']
// Thread owns 4 e-cols; 2 q's with interleaved f-chains. PDL: the qt/exp/bias
// preamble runs BEFORE the wait (overlaps kernel B), mp/ms loads after.
// 1024 CTAs (16 q each), 256 threads.
// ---------------------------------------------------------------------------
__global__ __launch_bounds__(256) void k_combine(
    const float* __restrict__ query_times,
    const float* __restrict__ log_sigma,
    const float* __restrict__ b_proj,
    float* __restrict__ out)
{
    const int tid = threadIdx.x;
    const int b   = blockIdx.y;
    const int q0  = blockIdx.x * 16;
    const int e   = (tid & 31) * 4;
    const int qh  = tid >> 5;          // 0..7, 2 q's each

    // ---- preamble (independent of B's output) ----
    const float* qtp = query_times + b * Q + q0 + qh * 2;
    const float qt0 = qtp[0];
    const float qt1 = qtp[1];
    const float c2 = __expf(-2.0f * log_sigma[0]);
    const float4 bp = *(const float4*)&b_proj[e];
    float f0 = __expf(-0.5f * c2 * qt0 * qt0);
    float f1 = __expf(-0.5f * c2 * qt1 * qt1);

    grid_dep_wait();   // B's g_Mp / g_msum now visible

    float4 mp[KT];
    float  ms[KT];
    const float* mpb = g_Mp + (size_t)b * KT * D + e;
    const float* msb = g_msum + b * KT;
#pragma unroll
    for (int k = 0; k < KT; ++k) {
        mp[k] = *(const float4*)(mpb + k * D);
        ms[k] = msb[k];
    }

    float* ob = out + ((size_t)(b * Q) + q0 + qh * 2) * D + e;

    float4 n0, n1;
    n0.x = f0 * mp[0].x; n0.y = f0 * mp[0].y; n0.z = f0 * mp[0].z; n0.w = f0 * mp[0].w;
    n1.x = f1 * mp[0].x; n1.y = f1 * mp[0].y; n1.z = f1 * mp[0].z; n1.w = f1 * mp[0].w;
    float d0 = f0 * ms[0];
    float d1 = f1 * ms[0];
#pragma unroll
    for (int k = 1; k < KT; ++k) {
        f0 *= qt0;
        f1 *= qt1;
        n0.x = fmaf(f0, mp[k].x, n0.x); n0.y = fmaf(f0, mp[k].y, n0.y);
        n0.z = fmaf(f0, mp[k].z, n0.z); n0.w = fmaf(f0, mp[k].w, n0.w);
        n1.x = fmaf(f1, mp[k].x, n1.x); n1.y = fmaf(f1, mp[k].y, n1.y);
        n1.z = fmaf(f1, mp[k].z, n1.z); n1.w = fmaf(f1, mp[k].w, n1.w);
        d0 = fmaf(f0, ms[k], d0);
        d1 = fmaf(f1, ms[k], d1);
    }
    const float i0 = __fdividef(1.0f, fmaxf(d0, 1e-8f));
    const float i1 = __fdividef(1.0f, fmaxf(d1, 1e-8f));
    float4 v0, v1;
    v0.x = fmaf(n0.x, i0, bp.x); v0.y = fmaf(n0.y, i0, bp.y);
    v0.z = fmaf(n0.z, i0, bp.z); v0.w = fmaf(n0.w, i0, bp.w);
    v1.x = fmaf(n1.x, i1, bp.x); v1.y = fmaf(n1.y, i1, bp.y);
    v1.z = fmaf(n1.z, i1, bp.z); v1.w = fmaf(n1.w, i1, bp.w);
    *(float4*)(ob)     = v0;
    *(float4*)(ob + D) = v1;
}

// ---------------------------------------------------------------------------
extern "C" void kernel_launch(void* const* d_in, const int* in_sizes, int n_in,
                              void* d_out, int out_size) {
    const float* obs_emb     = (const float*)d_in[0];
    const float* obs_times   = (const float*)d_in[1];
    const float* query_times = (const float*)d_in[2];
    const float* obs_mask    = (const float*)d_in[3];
    const float* log_sigma   = (const float*)d_in[4];
    const float* W_proj      = (const float*)d_in[5];
    const float* b_proj      = (const float*)d_in[6];
    float* out = (float*)d_out;

    // A: normal launch
    dim3 gA(NCH, B);
    k_moments<<<gA, 256>>>(obs_emb, obs_times, obs_mask, log_sigma);

    // B, C: programmatic dependent launches (overlap ramp with predecessor drain)
    cudaLaunchAttribute attr[1];
    attr[0].id = cudaLaunchAttributeProgrammaticStreamSerialization;
    attr[0].val.programmaticStreamSerializationAllowed = 1;

    {
        cudaLaunchConfig_t cfg = {};
        cfg.gridDim  = dim3(B * KT);
        cfg.blockDim = dim3(128);
        cfg.stream   = 0;
        cfg.attrs    = attr;
        cfg.numAttrs = 1;
        cudaLaunchKernelEx(&cfg, k_project, W_proj);
    }
    {
        cudaLaunchConfig_t cfg = {};
        cfg.gridDim  = dim3(Q / 16, B);
        cfg.blockDim = dim3(256);
        cfg.stream   = 0;
        cfg.attrs    = attr;
        cfg.numAttrs = 1;
        cudaLaunchKernelEx(&cfg, k_combine, query_times, log_sigma, b_proj, out);
    }
}